// round 3
// baseline (speedup 1.0000x reference)
#include <cuda_runtime.h>
#include <cstdint>

// ---------------------------------------------------------------------------
// SevenSacredNeurons fused kernel, round 3 (round-2 design, cleaned resubmit).
//   512 threads/CTA, 256 rows/CTA, K-split halves, f32x2 FMA, LDS128 weights.
// ---------------------------------------------------------------------------

#define PHI_F      1.6180339887498949f
#define INV_PHI_F  0.6180339887498949f

typedef unsigned long long ull;

static __device__ __forceinline__ ull pk2(float v) {
    ull r; asm("mov.b64 %0, {%1, %1};" : "=l"(r) : "f"(v)); return r;
}
static __device__ __forceinline__ void upk(ull v, float& lo, float& hi) {
    asm("mov.b64 {%0, %1}, %2;" : "=f"(lo), "=f"(hi) : "l"(v));
}
static __device__ __forceinline__ ull ffma2(ull a, ull b, ull c) {
    ull d; asm("fma.rn.f32x2 %0, %1, %2, %3;" : "=l"(d) : "l"(a), "l"(b), "l"(c));
    return d;
}
static __device__ __forceinline__ ull add2(ull a, ull b) {
    ull d; asm("add.rn.f32x2 %0, %1, %2;" : "=l"(d) : "l"(a), "l"(b));
    return d;
}
static __device__ __forceinline__ float phi_spiral(float x) {
    float e   = __expf(-x * INV_PHI_F);
    float den = (1.0f + e) * (1.0f + fabsf(x));
    return x * PHI_F * __fdividef(1.0f, den);
}

// ---- shared memory layout (floats) -----------------------------------------
// WS1  [256][64]  stage1 weights transposed, cols padded 49->64
// XH   [64][256]  x chunk / H planes / stage2 PSUM / stage3 partial exchange
// CS   [64][256]  stage1 PSUM / combined planes
// WN2  [49][64]   stage2 weights transposed, padded
// WINT [21][52]   stage3 weights row-major, i padded 49->52
static constexpr int OFF_WS1  = 0;
static constexpr int OFF_XH   = 16384;
static constexpr int OFF_CS   = 32768;
static constexpr int OFF_WN2  = 49152;
static constexpr int OFF_WINT = 52288;
static constexpr int OFF_BIN  = 53380;
static constexpr int OFF_BN   = 53444;
static constexpr int OFF_BINT = 53508;
static constexpr int OFF_GAM  = 53529;
static constexpr int OFF_BET  = 53550;
static constexpr int OFF_WOUT = 53571;
static constexpr int OFF_BOUT = 53655;
static constexpr int SMEM_FLOATS = 53659;
static constexpr int SMEM_BYTES  = SMEM_FLOATS * 4;   // 214636 B < 227 KB

// ---- 4-row x 16-col FMA block (8 f32x2 col-pairs per row) ------------------
static __device__ __forceinline__ void fma_block(const ulonglong2* __restrict__ wp,
                                                 ull x0, ull x1, ull x2, ull x3,
                                                 ull acc[32]) {
    ulonglong2 wA = wp[0], wB = wp[1], wC = wp[2], wD = wp[3];
    const ull w0 = wA.x, w1 = wA.y, w2 = wB.x, w3 = wB.y;
    const ull w4 = wC.x, w5 = wC.y, w6 = wD.x, w7 = wD.y;
    acc[0]  = ffma2(x0, w0, acc[0]);
    acc[1]  = ffma2(x0, w1, acc[1]);
    acc[2]  = ffma2(x0, w2, acc[2]);
    acc[3]  = ffma2(x0, w3, acc[3]);
    acc[4]  = ffma2(x0, w4, acc[4]);
    acc[5]  = ffma2(x0, w5, acc[5]);
    acc[6]  = ffma2(x0, w6, acc[6]);
    acc[7]  = ffma2(x0, w7, acc[7]);
    acc[8]  = ffma2(x1, w0, acc[8]);
    acc[9]  = ffma2(x1, w1, acc[9]);
    acc[10] = ffma2(x1, w2, acc[10]);
    acc[11] = ffma2(x1, w3, acc[11]);
    acc[12] = ffma2(x1, w4, acc[12]);
    acc[13] = ffma2(x1, w5, acc[13]);
    acc[14] = ffma2(x1, w6, acc[14]);
    acc[15] = ffma2(x1, w7, acc[15]);
    acc[16] = ffma2(x2, w0, acc[16]);
    acc[17] = ffma2(x2, w1, acc[17]);
    acc[18] = ffma2(x2, w2, acc[18]);
    acc[19] = ffma2(x2, w3, acc[19]);
    acc[20] = ffma2(x2, w4, acc[20]);
    acc[21] = ffma2(x2, w5, acc[21]);
    acc[22] = ffma2(x2, w6, acc[22]);
    acc[23] = ffma2(x2, w7, acc[23]);
    acc[24] = ffma2(x3, w0, acc[24]);
    acc[25] = ffma2(x3, w1, acc[25]);
    acc[26] = ffma2(x3, w2, acc[26]);
    acc[27] = ffma2(x3, w3, acc[27]);
    acc[28] = ffma2(x3, w4, acc[28]);
    acc[29] = ffma2(x3, w5, acc[29]);
    acc[30] = ffma2(x3, w6, acc[30]);
    acc[31] = ffma2(x3, w7, acc[31]);
}

// ---- GEMM microkernel: 4 rows x 16 cols per thread -------------------------
// sW  : [K][64] weights; sX4 : [K][64] float4 row-groups, slot rg^((i>>3)&7)
template <int OCT, int IBEG, bool TAIL>
static __device__ __forceinline__ void gemm16(const float* __restrict__ sW,
                                              const float4* __restrict__ sX4,
                                              int rg, int cg, ull acc[32]) {
    const float*  wb = sW  + IBEG * 64 + cg * 16;
    const float4* xb = sX4 + IBEG * 64;
#pragma unroll
    for (int o = 0; o < OCT; ++o) {
        const int s = ((IBEG >> 3) + o) & 7;
        const float4* xo = xb + o * 512 + (rg ^ s);
        const float*  wo = wb + o * 512;
#pragma unroll
        for (int u = 0; u < 8; ++u) {
            float4 xv = xo[u * 64];
            ull x0 = pk2(xv.x), x1 = pk2(xv.y), x2 = pk2(xv.z), x3 = pk2(xv.w);
            fma_block(reinterpret_cast<const ulonglong2*>(wo + u * 64),
                      x0, x1, x2, x3, acc);
        }
    }
    if (TAIL) {
        const int i = IBEG + OCT * 8;
        const int s = (i >> 3) & 7;
        float4 xv = sX4[i * 64 + (rg ^ s)];
        ull x0 = pk2(xv.x), x1 = pk2(xv.y), x2 = pk2(xv.z), x3 = pk2(xv.w);
        fma_block(reinterpret_cast<const ulonglong2*>(sW + i * 64 + cg * 16),
                  x0, x1, x2, x3, acc);
    }
}

// epilogue: +bias, phi, write transposed+swizzled planes [j][row] float4
static __device__ __forceinline__ void epilogue16(const ull acc[32],
                                                  const float* __restrict__ sBias,
                                                  float4* __restrict__ dst4,
                                                  int rg, int cg) {
#pragma unroll
    for (int p = 0; p < 8; ++p) {
        int j0 = cg * 16 + 2 * p;
        float b0 = sBias[j0], b1 = sBias[j0 + 1];
        float l0, h0, l1, h1, l2, h2, l3, h3;
        upk(acc[p],      l0, h0);
        upk(acc[8 + p],  l1, h1);
        upk(acc[16 + p], l2, h2);
        upk(acc[24 + p], l3, h3);
        float4 v0 = make_float4(phi_spiral(l0 + b0), phi_spiral(l1 + b0),
                                phi_spiral(l2 + b0), phi_spiral(l3 + b0));
        float4 v1 = make_float4(phi_spiral(h0 + b1), phi_spiral(h1 + b1),
                                phi_spiral(h2 + b1), phi_spiral(h3 + b1));
        dst4[j0 * 64 + (rg ^ ((j0 >> 3) & 7))] = v0;
        dst4[(j0 + 1) * 64 + (rg ^ (((j0 + 1) >> 3) & 7))] = v1;
    }
}

__global__ __launch_bounds__(512, 1)
void sacred_kernel(const float* __restrict__ x,
                   const float* __restrict__ W_in,  const float* __restrict__ b_in,
                   const float* __restrict__ Wn,    const float* __restrict__ bn,
                   const float* __restrict__ W_int, const float* __restrict__ b_int,
                   const float* __restrict__ gamma, const float* __restrict__ beta,
                   const float* __restrict__ W_out, const float* __restrict__ b_out,
                   float* __restrict__ out) {
    extern __shared__ float sm[];
    const int tid  = threadIdx.x;
    const int half = tid >> 8;          // K-split half
    const int tidH = tid & 255;
    const int rg   = tidH & 63;         // row group (4 rows) 0..63
    const int cg   = tidH >> 6;         // col group (16 cols) 0..3
    const long long rowBase = (long long)blockIdx.x * 256;

    float*  sWS1  = sm + OFF_WS1;
    float*  sWN2  = sm + OFF_WN2;
    float*  sWINT = sm + OFF_WINT;
    float*  sBIN  = sm + OFF_BIN;
    float*  sBN   = sm + OFF_BN;
    float*  sBINT = sm + OFF_BINT;
    float*  sGAM  = sm + OFF_GAM;
    float*  sBET  = sm + OFF_BET;
    float*  sWOUT = sm + OFF_WOUT;
    float*  sBOUT = sm + OFF_BOUT;
    float*  XHf   = sm + OFF_XH;
    float4* XH4   = reinterpret_cast<float4*>(sm + OFF_XH);
    float4* CS4   = reinterpret_cast<float4*>(sm + OFF_CS);
    const float* CSf = sm + OFF_CS;

    // ---- weight staging ----------------------------------------------------
    for (int k = tid; k < 16384; k += 512) sWS1[k] = 0.0f;
    for (int k = tid; k < 3136;  k += 512) sWN2[k] = 0.0f;
    for (int k = tid; k < 1092;  k += 512) sWINT[k] = 0.0f;
    if (tid < 64) { sBIN[tid] = 0.0f; sBN[tid] = 0.0f; }
    __syncthreads();

    for (int k = tid; k < 49 * 256; k += 512) {
        int j = k >> 8, i = k & 255;
        sWS1[i * 64 + j] = W_in[k];
    }
    for (int k = tid; k < 49 * 49; k += 512) {
        int j = k / 49, i = k - j * 49;
        sWN2[i * 64 + j] = Wn[k];
    }
    for (int k = tid; k < 21 * 49; k += 512) {
        int j = k / 49, i = k - j * 49;
        sWINT[j * 52 + i] = W_int[k];
    }
    if (tid < 49) { sBIN[tid] = b_in[tid]; sBN[tid] = bn[tid]; }
    if (tid < 21) { sBINT[tid] = b_int[tid]; sGAM[tid] = gamma[tid]; sBET[tid] = beta[tid]; }
    if (tid < 84) sWOUT[tid] = W_out[tid];
    if (tid < 4)  sBOUT[tid] = b_out[tid];
    // first staging __syncthreads below covers visibility

    // ---- stage 1: x @ W_in^T, K=256 in 4 chunks of 64, halves split 32/32 --
    ull acc[32];
#pragma unroll
    for (int q = 0; q < 32; ++q) acc[q] = 0ull;

    for (int c = 0; c < 4; ++c) {
#pragma unroll
        for (int it = 0; it < 8; ++it) {
            int f   = it * 512 + tid;
            int row = f >> 4;
            int i0  = (f & 15) << 2;
            float4 v = *reinterpret_cast<const float4*>(
                x + (rowBase + row) * 256 + c * 64 + i0);
            int q8 = row >> 2, rr = row & 3;
            int s  = (i0 >> 3) & 7;          // same for i0..i0+3
            int slotw = ((q8 ^ s) << 2) + rr;
            XHf[(i0 + 0) * 256 + slotw] = v.x;
            XHf[(i0 + 1) * 256 + slotw] = v.y;
            XHf[(i0 + 2) * 256 + slotw] = v.z;
            XHf[(i0 + 3) * 256 + slotw] = v.w;
        }
        __syncthreads();
        const float* sWc = sWS1 + c * 64 * 64;
        if (half == 0) gemm16<4, 0,  false>(sWc, XH4, rg, cg, acc);
        else           gemm16<4, 32, false>(sWc, XH4, rg, cg, acc);
        __syncthreads();
    }

    // stage1 cross-half reduce + epilogue -> H planes in XH
    {
        ull* PS1 = reinterpret_cast<ull*>(sm + OFF_CS);
        if (half) {
#pragma unroll
            for (int q = 0; q < 32; ++q) PS1[q * 256 + tidH] = acc[q];
        }
        __syncthreads();
        if (!half) {
#pragma unroll
            for (int q = 0; q < 32; ++q) acc[q] = add2(acc[q], PS1[q * 256 + tidH]);
            epilogue16(acc, sBIN, XH4, rg, cg);
        }
        __syncthreads();
    }

    // ---- stage 2: combined = phi(h @ Wn^T + bn), K=49 split 24/25 ----------
#pragma unroll
    for (int q = 0; q < 32; ++q) acc[q] = 0ull;
    if (half == 0) gemm16<3, 0,  false>(sWN2, XH4, rg, cg, acc);
    else           gemm16<3, 24, true >(sWN2, XH4, rg, cg, acc);
    __syncthreads();
    {
        ull* PS2 = reinterpret_cast<ull*>(sm + OFF_XH);   // H dead now
        if (half) {
#pragma unroll
            for (int q = 0; q < 32; ++q) PS2[q * 256 + tidH] = acc[q];
        }
        __syncthreads();
        if (!half) {
#pragma unroll
            for (int q = 0; q < 32; ++q) acc[q] = add2(acc[q], PS2[q * 256 + tidH]);
            epilogue16(acc, sBN, CS4, rg, cg);
        }
        __syncthreads();
    }

    // ---- stage 3 + LN + stage 4: one row per thread-pair -------------------
    {
        const int row = tidH;
        float* PARTf = sm + OFF_XH;       // stage2 PSUM dead
        float part[21];
        const float4* W4 = reinterpret_cast<const float4*>(sWINT);

        if (half == 0) {
            float cv[24];
#pragma unroll
            for (int i = 0; i < 24; ++i)
                cv[i] = CSf[i * 256 + (((row >> 2) ^ ((i >> 3) & 7)) << 2) + (row & 3)];
#pragma unroll
            for (int j = 0; j < 21; ++j) {
                float a = sBINT[j];
#pragma unroll
                for (int qq = 0; qq < 6; ++qq) {
                    float4 w = W4[j * 13 + qq];
                    a = fmaf(cv[4 * qq],     w.x, a);
                    a = fmaf(cv[4 * qq + 1], w.y, a);
                    a = fmaf(cv[4 * qq + 2], w.z, a);
                    a = fmaf(cv[4 * qq + 3], w.w, a);
                }
                part[j] = a;
            }
        } else {
            float cv[25];
#pragma unroll
            for (int i = 0; i < 25; ++i) {
                int ii = 24 + i;
                cv[i] = CSf[ii * 256 + (((row >> 2) ^ ((ii >> 3) & 7)) << 2) + (row & 3)];
            }
#pragma unroll
            for (int j = 0; j < 21; ++j) {
                float a = 0.0f;
#pragma unroll
                for (int qq = 0; qq < 6; ++qq) {
                    float4 w = W4[j * 13 + 6 + qq];
                    a = fmaf(cv[4 * qq],     w.x, a);
                    a = fmaf(cv[4 * qq + 1], w.y, a);
                    a = fmaf(cv[4 * qq + 2], w.z, a);
                    a = fmaf(cv[4 * qq + 3], w.w, a);
                }
                a = fmaf(cv[24], sWINT[j * 52 + 48], a);
                part[j] = a;
            }
#pragma unroll
            for (int j = 0; j < 21; ++j) PARTf[j * 256 + row] = part[j];
        }
        __syncthreads();

        if (half == 0) {
            float t[21];
            float ssum = 0.0f;
#pragma unroll
            for (int j = 0; j < 21; ++j) {
                float v = phi_spiral(part[j] + PARTf[j * 256 + row]);
                t[j] = v;
                ssum += v;
            }
            float mu = ssum * (1.0f / 21.0f);
            float vs = 0.0f;
#pragma unroll
            for (int j = 0; j < 21; ++j) { float d = t[j] - mu; vs = fmaf(d, d, vs); }
            float rs = rsqrtf(vs * (1.0f / 21.0f) + 1e-5f);

            float o0 = sBOUT[0], o1 = sBOUT[1], o2 = sBOUT[2], o3 = sBOUT[3];
#pragma unroll
            for (int j = 0; j < 21; ++j) {
                float n = (t[j] - mu) * rs;
                n = fmaf(n, sGAM[j], sBET[j]);
                o0 = fmaf(n, sWOUT[j],      o0);
                o1 = fmaf(n, sWOUT[21 + j], o1);
                o2 = fmaf(n, sWOUT[42 + j], o2);
                o3 = fmaf(n, sWOUT[63 + j], o3);
            }
            reinterpret_cast<float4*>(out)[rowBase + row] = make_float4(o0, o1, o2, o3);
        }
    }
}

extern "C" void kernel_launch(void* const* d_in, const int* in_sizes, int n_in,
                              void* d_out, int out_size) {
    const float* x     = (const float*)d_in[0];
    const float* W_in  = (const float*)d_in[1];
    const float* b_in  = (const float*)d_in[2];
    const float* Wn    = (const float*)d_in[3];
    const float* bn    = (const float*)d_in[4];
    const float* W_int = (const float*)d_in[5];
    const float* b_int = (const float*)d_in[6];
    const float* gamma = (const float*)d_in[7];
    const float* beta  = (const float*)d_in[8];
    const float* W_out = (const float*)d_in[9];
    const float* b_out = (const float*)d_in[10];

    long long rows = (long long)in_sizes[0] / 256;   // 262144
    int grid = (int)(rows / 256);                    // 1024

    cudaFuncSetAttribute(sacred_kernel,
                         cudaFuncAttributeMaxDynamicSharedMemorySize, SMEM_BYTES);
    sacred_kernel<<<grid, 512, SMEM_BYTES>>>(x, W_in, b_in, Wn, bn, W_int, b_int,
                                             gamma, beta, W_out, b_out,
                                             (float*)d_out);
}

// round 4
// speedup vs baseline: 1.0918x; 1.0918x over previous
#include <cuda_runtime.h>
#include <cstdint>

// ---------------------------------------------------------------------------
// SevenSacredNeurons fused kernel, round 4.
//   512 threads/CTA, 256 rows/CTA, NO K-split.
//   Tile: 2 rows x 16 cols per thread (128 row-pairs x 4 col-groups).
//   acc[16] f32x2 accumulators -> ~80 regs, no spills at the 128-reg cap.
// ---------------------------------------------------------------------------

#define PHI_F      1.6180339887498949f
#define INV_PHI_F  0.6180339887498949f

typedef unsigned long long ull;

static __device__ __forceinline__ ull pk2(float v) {
    ull r; asm("mov.b64 %0, {%1, %1};" : "=l"(r) : "f"(v)); return r;
}
static __device__ __forceinline__ void upk(ull v, float& lo, float& hi) {
    asm("mov.b64 {%0, %1}, %2;" : "=f"(lo), "=f"(hi) : "l"(v));
}
static __device__ __forceinline__ ull ffma2(ull a, ull b, ull c) {
    ull d; asm("fma.rn.f32x2 %0, %1, %2, %3;" : "=l"(d) : "l"(a), "l"(b), "l"(c));
    return d;
}
static __device__ __forceinline__ float phi_spiral(float x) {
    float e   = __expf(-x * INV_PHI_F);
    float den = (1.0f + e) * (1.0f + fabsf(x));
    return x * PHI_F * __fdividef(1.0f, den);
}

// ---- shared memory layout (floats) -----------------------------------------
// WS1  [256][64]  stage1 weights transposed, cols padded 49->64       64 KB
// XH   [64][256]  x chunk planes / H planes / stage3 partial exchange 64 KB
// CS   [64][256]  combined planes (stage2 out)                        64 KB
// WN2  [49][64]   stage2 weights transposed, padded                   12.25 KB
// WINT [21][52]   stage3 weights row-major, i padded 49->52
static constexpr int OFF_WS1  = 0;
static constexpr int OFF_XH   = 16384;
static constexpr int OFF_CS   = 32768;
static constexpr int OFF_WN2  = 49152;
static constexpr int OFF_WINT = 52288;
static constexpr int OFF_BIN  = 53380;
static constexpr int OFF_BN   = 53444;
static constexpr int OFF_BINT = 53508;
static constexpr int OFF_GAM  = 53529;
static constexpr int OFF_BET  = 53550;
static constexpr int OFF_WOUT = 53571;
static constexpr int OFF_BOUT = 53655;
static constexpr int SMEM_FLOATS = 53659;
static constexpr int SMEM_BYTES  = SMEM_FLOATS * 4;   // 214636 B < 227 KB

// ---- 2-row x 16-col FMA block (8 f32x2 col-pairs per row) ------------------
static __device__ __forceinline__ void fma_block2(const ulonglong2* __restrict__ wp,
                                                  ull x0, ull x1, ull acc[16]) {
    ulonglong2 wA = wp[0], wB = wp[1], wC = wp[2], wD = wp[3];
    const ull w0 = wA.x, w1 = wA.y, w2 = wB.x, w3 = wB.y;
    const ull w4 = wC.x, w5 = wC.y, w6 = wD.x, w7 = wD.y;
    acc[0]  = ffma2(x0, w0, acc[0]);
    acc[1]  = ffma2(x0, w1, acc[1]);
    acc[2]  = ffma2(x0, w2, acc[2]);
    acc[3]  = ffma2(x0, w3, acc[3]);
    acc[4]  = ffma2(x0, w4, acc[4]);
    acc[5]  = ffma2(x0, w5, acc[5]);
    acc[6]  = ffma2(x0, w6, acc[6]);
    acc[7]  = ffma2(x0, w7, acc[7]);
    acc[8]  = ffma2(x1, w0, acc[8]);
    acc[9]  = ffma2(x1, w1, acc[9]);
    acc[10] = ffma2(x1, w2, acc[10]);
    acc[11] = ffma2(x1, w3, acc[11]);
    acc[12] = ffma2(x1, w4, acc[12]);
    acc[13] = ffma2(x1, w5, acc[13]);
    acc[14] = ffma2(x1, w6, acc[14]);
    acc[15] = ffma2(x1, w7, acc[15]);
}

// ---- GEMM microkernel: 2 rows x 16 cols per thread, full-K -----------------
// sW  : [K][64] weights; sXf : planes of 256 floats, float2 slot (r>>1)^s(i)
template <int OCT, bool TAIL>
static __device__ __forceinline__ void gemm2(const float* __restrict__ sW,
                                             const float* __restrict__ sXf,
                                             int rg, int cg, ull acc[16]) {
    const float* wb = sW + cg * 16;
#pragma unroll
    for (int o = 0; o < OCT; ++o) {
        const int s = o & 7;
#pragma unroll
        for (int u = 0; u < 8; ++u) {
            const int i = o * 8 + u;
            float2 xv = reinterpret_cast<const float2*>(sXf + i * 256)[rg ^ s];
            ull x0 = pk2(xv.x), x1 = pk2(xv.y);
            fma_block2(reinterpret_cast<const ulonglong2*>(wb + i * 64), x0, x1, acc);
        }
    }
    if (TAIL) {
        const int i = OCT * 8;
        const int s = (i >> 3) & 7;
        float2 xv = reinterpret_cast<const float2*>(sXf + i * 256)[rg ^ s];
        ull x0 = pk2(xv.x), x1 = pk2(xv.y);
        fma_block2(reinterpret_cast<const ulonglong2*>(wb + i * 64), x0, x1, acc);
    }
}

// epilogue: +bias, phi, write transposed planes [j][256] as float2 (2 rows)
static __device__ __forceinline__ void epilogue2(const ull acc[16],
                                                 const float* __restrict__ sBias,
                                                 float* __restrict__ dstf,
                                                 int rg, int cg) {
#pragma unroll
    for (int p = 0; p < 8; ++p) {
        int j0 = cg * 16 + 2 * p;
        float b0 = sBias[j0], b1 = sBias[j0 + 1];
        float r0c0, r0c1, r1c0, r1c1;
        upk(acc[p],     r0c0, r0c1);
        upk(acc[8 + p], r1c0, r1c1);
        float2 v0 = make_float2(phi_spiral(r0c0 + b0), phi_spiral(r1c0 + b0));
        float2 v1 = make_float2(phi_spiral(r0c1 + b1), phi_spiral(r1c1 + b1));
        int s0 = (j0 >> 3) & 7;
        int s1 = ((j0 + 1) >> 3) & 7;
        reinterpret_cast<float2*>(dstf + j0 * 256)[rg ^ s0]       = v0;
        reinterpret_cast<float2*>(dstf + (j0 + 1) * 256)[rg ^ s1] = v1;
    }
}

__global__ __launch_bounds__(512, 1)
void sacred_kernel(const float* __restrict__ x,
                   const float* __restrict__ W_in,  const float* __restrict__ b_in,
                   const float* __restrict__ Wn,    const float* __restrict__ bn,
                   const float* __restrict__ W_int, const float* __restrict__ b_int,
                   const float* __restrict__ gamma, const float* __restrict__ beta,
                   const float* __restrict__ W_out, const float* __restrict__ b_out,
                   float* __restrict__ out) {
    extern __shared__ float sm[];
    const int tid = threadIdx.x;
    const int rg  = tid & 127;          // row pair 0..127 (rows 2rg, 2rg+1)
    const int cg  = tid >> 7;           // col group (16 cols) 0..3
    const long long rowBase = (long long)blockIdx.x * 256;

    float*  sWS1  = sm + OFF_WS1;
    float*  sWN2  = sm + OFF_WN2;
    float*  sWINT = sm + OFF_WINT;
    float*  sBIN  = sm + OFF_BIN;
    float*  sBN   = sm + OFF_BN;
    float*  sBINT = sm + OFF_BINT;
    float*  sGAM  = sm + OFF_GAM;
    float*  sBET  = sm + OFF_BET;
    float*  sWOUT = sm + OFF_WOUT;
    float*  sBOUT = sm + OFF_BOUT;
    float*  XHf   = sm + OFF_XH;
    float*  CSf   = sm + OFF_CS;

    // ---- weight staging ----------------------------------------------------
    for (int k = tid; k < 16384; k += 512) sWS1[k] = 0.0f;
    for (int k = tid; k < 3136;  k += 512) sWN2[k] = 0.0f;
    for (int k = tid; k < 1092;  k += 512) sWINT[k] = 0.0f;
    if (tid < 64) { sBIN[tid] = 0.0f; sBN[tid] = 0.0f; }
    __syncthreads();

    for (int k = tid; k < 49 * 256; k += 512) {
        int j = k >> 8, i = k & 255;
        sWS1[i * 64 + j] = W_in[k];
    }
    for (int k = tid; k < 49 * 49; k += 512) {
        int j = k / 49, i = k - j * 49;
        sWN2[i * 64 + j] = Wn[k];
    }
    for (int k = tid; k < 21 * 49; k += 512) {
        int j = k / 49, i = k - j * 49;
        sWINT[j * 52 + i] = W_int[k];
    }
    if (tid < 49) { sBIN[tid] = b_in[tid]; sBN[tid] = bn[tid]; }
    if (tid < 21) { sBINT[tid] = b_int[tid]; sGAM[tid] = gamma[tid]; sBET[tid] = beta[tid]; }
    if (tid < 84) sWOUT[tid] = W_out[tid];
    if (tid < 4)  sBOUT[tid] = b_out[tid];
    // first loader __syncthreads below covers visibility

    // ---- stage 1: x @ W_in^T, K=256 in 4 chunks of 64 ----------------------
    ull acc[16];
#pragma unroll
    for (int q = 0; q < 16; ++q) acc[q] = 0ull;

    for (int c = 0; c < 4; ++c) {
        // coalesced global load, transposed store into planes XH[i][256]
#pragma unroll
        for (int it = 0; it < 8; ++it) {
            int f   = it * 512 + tid;        // 0..4095
            int row = f >> 4;                // 0..255
            int i0  = (f & 15) << 2;         // 0..60
            float4 v = *reinterpret_cast<const float4*>(
                x + (rowBase + row) * 256 + c * 64 + i0);
            int s = (i0 >> 3) & 7;           // same for i0..i0+3
            int pos = (((row >> 1) ^ s) << 1) + (row & 1);
            XHf[(i0 + 0) * 256 + pos] = v.x;
            XHf[(i0 + 1) * 256 + pos] = v.y;
            XHf[(i0 + 2) * 256 + pos] = v.z;
            XHf[(i0 + 3) * 256 + pos] = v.w;
        }
        __syncthreads();
        gemm2<8, false>(sWS1 + c * 4096, XHf, rg, cg, acc);
        __syncthreads();
    }
    // h = phi(acc + b_in) -> H planes in XH (x data dead)
    epilogue2(acc, sBIN, XHf, rg, cg);
    __syncthreads();

    // ---- stage 2: combined = phi(h @ Wn^T + bn), K=49 ----------------------
#pragma unroll
    for (int q = 0; q < 16; ++q) acc[q] = 0ull;
    gemm2<6, true>(sWN2, XHf, rg, cg, acc);
    __syncthreads();                         // all reads of H done
    epilogue2(acc, sBN, CSf, rg, cg);
    __syncthreads();

    // ---- stage 3 + LN + stage 4: one row per thread-pair (i-split) ---------
    {
        const int half = tid >> 8;
        const int row  = tid & 255;
        float* PARTf = XHf;                  // H planes dead now
        float part[21];
        const float4* W4 = reinterpret_cast<const float4*>(sWINT);

        if (half == 0) {
            float cv[24];
#pragma unroll
            for (int i = 0; i < 24; ++i)
                cv[i] = CSf[i * 256 + (((row >> 1) ^ ((i >> 3) & 7)) << 1) + (row & 1)];
#pragma unroll
            for (int j = 0; j < 21; ++j) {
                float a = sBINT[j];
#pragma unroll
                for (int qq = 0; qq < 6; ++qq) {
                    float4 w = W4[j * 13 + qq];
                    a = fmaf(cv[4 * qq],     w.x, a);
                    a = fmaf(cv[4 * qq + 1], w.y, a);
                    a = fmaf(cv[4 * qq + 2], w.z, a);
                    a = fmaf(cv[4 * qq + 3], w.w, a);
                }
                part[j] = a;
            }
        } else {
            float cv[25];
#pragma unroll
            for (int i = 0; i < 25; ++i) {
                int ii = 24 + i;
                cv[i] = CSf[ii * 256 + (((row >> 1) ^ ((ii >> 3) & 7)) << 1) + (row & 1)];
            }
#pragma unroll
            for (int j = 0; j < 21; ++j) {
                float a = 0.0f;
#pragma unroll
                for (int qq = 0; qq < 6; ++qq) {
                    float4 w = W4[j * 13 + 6 + qq];
                    a = fmaf(cv[4 * qq],     w.x, a);
                    a = fmaf(cv[4 * qq + 1], w.y, a);
                    a = fmaf(cv[4 * qq + 2], w.z, a);
                    a = fmaf(cv[4 * qq + 3], w.w, a);
                }
                a = fmaf(cv[24], sWINT[j * 52 + 48], a);
                part[j] = a;
            }
#pragma unroll
            for (int j = 0; j < 21; ++j) PARTf[j * 256 + row] = part[j];
        }
        __syncthreads();

        if (half == 0) {
            float t[21];
            float ssum = 0.0f;
#pragma unroll
            for (int j = 0; j < 21; ++j) {
                float v = phi_spiral(part[j] + PARTf[j * 256 + row]);
                t[j] = v;
                ssum += v;
            }
            float mu = ssum * (1.0f / 21.0f);
            float vs = 0.0f;
#pragma unroll
            for (int j = 0; j < 21; ++j) { float d = t[j] - mu; vs = fmaf(d, d, vs); }
            float rs = rsqrtf(vs * (1.0f / 21.0f) + 1e-5f);

            float o0 = sBOUT[0], o1 = sBOUT[1], o2 = sBOUT[2], o3 = sBOUT[3];
#pragma unroll
            for (int j = 0; j < 21; ++j) {
                float n = (t[j] - mu) * rs;
                n = fmaf(n, sGAM[j], sBET[j]);
                o0 = fmaf(n, sWOUT[j],      o0);
                o1 = fmaf(n, sWOUT[21 + j], o1);
                o2 = fmaf(n, sWOUT[42 + j], o2);
                o3 = fmaf(n, sWOUT[63 + j], o3);
            }
            reinterpret_cast<float4*>(out)[rowBase + row] = make_float4(o0, o1, o2, o3);
        }
    }
}

extern "C" void kernel_launch(void* const* d_in, const int* in_sizes, int n_in,
                              void* d_out, int out_size) {
    const float* x     = (const float*)d_in[0];
    const float* W_in  = (const float*)d_in[1];
    const float* b_in  = (const float*)d_in[2];
    const float* Wn    = (const float*)d_in[3];
    const float* bn    = (const float*)d_in[4];
    const float* W_int = (const float*)d_in[5];
    const float* b_int = (const float*)d_in[6];
    const float* gamma = (const float*)d_in[7];
    const float* beta  = (const float*)d_in[8];
    const float* W_out = (const float*)d_in[9];
    const float* b_out = (const float*)d_in[10];

    long long rows = (long long)in_sizes[0] / 256;   // 262144
    int grid = (int)(rows / 256);                    // 1024

    cudaFuncSetAttribute(sacred_kernel,
                         cudaFuncAttributeMaxDynamicSharedMemorySize, SMEM_BYTES);
    sacred_kernel<<<grid, 512, SMEM_BYTES>>>(x, W_in, b_in, Wn, bn, W_int, b_int,
                                             gamma, beta, W_out, b_out,
                                             (float*)d_out);
}